// round 15
// baseline (speedup 1.0000x reference)
#include <cuda_runtime.h>
#include <cstdint>

#define BB   8
#define NN   128
#define COOR 3
#define FF   128
#define FILT 128

// Scratch: C = x @ w2 only. A' is now computed inside phase 2 (each block
// needs just 12 A'-rows -> zero chip-wide redundancy, no global round-trip).
__device__ float g_C[BB * NN * COOR * FILT];

// ---- packed f32x2 helpers --------------------------------------------------
typedef unsigned long long ull;

union F4U {
    float4 f4;
    ull    u[2];
};
union F2U {
    float2 f2;
    ull    u;
};

__device__ __forceinline__ ull fma2(ull a, ull b, ull c) {
    ull r;
    asm("fma.rn.f32x2 %0, %1, %2, %3;" : "=l"(r) : "l"(a), "l"(b), "l"(c));
    return r;
}
__device__ __forceinline__ ull pack2(float lo, float hi) {
    ull r;
    asm("mov.b64 %0, {%1, %2};" : "=l"(r) : "r"(__float_as_uint(lo)), "r"(__float_as_uint(hi)));
    return r;
}

// ---------------------------------------------------------------------------
// Phase 1 (C ONLY): C[row, k] = sum_f x[row, f] * w2[f, k]
// R7 shape verbatim (20.8 warps/SM, kh-split, DEPTH-8 prefetch) minus the
// A half: 1 LDG.64 + 2 LDS + 2 fma2 per f-iter. w-wavefronts halve
// (201 -> 100 MB chip) -> predict ~5-6us (was 11.4 for A+C).
// x pre-packed as (x,x) f32x2 in smem (no pack MOVs in the loop).
// ---------------------------------------------------------------------------
__global__ __launch_bounds__(128) void phase1_kernel(
    const float* __restrict__ x,   // [3072, 128]
    const float* __restrict__ w)   // [256, 128] (w2 = rows 128..255)
{
    constexpr int RT    = 8;             // rows per block
    constexpr int DEPTH = 8;             // w2-prefetch pipeline depth
    const int r0   = blockIdx.x * RT;
    const int kh   = blockIdx.y * 64;    // k half
    const int warp = threadIdx.x >> 5;   // 0..3
    const int lane = threadIdx.x & 31;
    const int k    = kh + lane * 2;      // this thread's k-pair
    const int wr   = warp * 2;           // first of this warp's 2 rows

    __shared__ ull xs2[RT * FF];         // pre-packed (x,x): 8 KB

    {
        const float4* xin = reinterpret_cast<const float4*>(x + (size_t)r0 * FF);
        #pragma unroll
        for (int t = threadIdx.x; t < RT * FF / 4; t += 128) {
            const float4 v = xin[t];
            ulonglong2* dst = reinterpret_cast<ulonglong2*>(&xs2[4 * t]);
            dst[0] = make_ulonglong2(pack2(v.x, v.x), pack2(v.y, v.y));
            dst[1] = make_ulonglong2(pack2(v.z, v.z), pack2(v.w, v.w));
        }
    }
    __syncthreads();

    ull acc0 = 0ull, acc1 = 0ull;

    const float* w2base = w + (size_t)FF * FILT + k;

    F2U W2[DEPTH];
    #pragma unroll
    for (int d = 0; d < DEPTH; d++)
        W2[d].f2 = *reinterpret_cast<const float2*>(w2base + (size_t)d * FILT);

    const ull* x0 = &xs2[(wr + 0) * FF];
    const ull* x1 = &xs2[(wr + 1) * FF];

    #pragma unroll 8
    for (int f = 0; f < FF; f++) {
        const int slot = f % DEPTH;
        const ull w2v = W2[slot].u;

        acc0 = fma2(x0[f], w2v, acc0);
        acc1 = fma2(x1[f], w2v, acc1);

        if (f + DEPTH < FF)
            W2[slot].f2 = *reinterpret_cast<const float2*>(w2base + (size_t)(f + DEPTH) * FILT);
    }

    F2U o0; o0.u = acc0;
    F2U o1; o1.u = acc1;
    *reinterpret_cast<float2*>(&g_C[(size_t)(r0 + wr + 0) * FILT + k]) = o0.f2;
    *reinterpret_cast<float2*>(&g_C[(size_t)(r0 + wr + 1) * FILT + k]) = o1.f2;
}

// ---------------------------------------------------------------------------
// Phase 2: out[b,i,j,k] = sum_c (A'[b,i,c,k] + C[b,j,c,k]) * d[b,i,j,c]
// Body = R4 config VERBATIM (local optimum: 16.4us). NEW PROLOGUE computes
// this block's own 12 A'-rows (A' = x@w1 + bv): ty owns row ty (+ row ty+8
// for ty<4); fma2 on pre-packed x; w1 quad loads L1-broadcast across ty.
// ~2us per block wave, replacing ~5.7us of phase-1 A work. Same per-lane
// f-order and bv init -> bitwise-identical A'.
// ---------------------------------------------------------------------------
__global__ __launch_bounds__(256, 2) void phase2_kernel(
    const float* __restrict__ x,     // [B, N, COOR, F]
    const float* __restrict__ w,     // [256, 128] (w1 = rows 0..127)
    const float* __restrict__ bv,    // [128]
    const float* __restrict__ dist,  // [B, N, N, COOR]
    float* __restrict__ out)         // [B, N, N, FILT]
{
    constexpr int TI = 4;
    constexpr int NROWS = TI * COOR;  // 12 A'-rows per block
    const int b  = blockIdx.y;
    const int i0 = blockIdx.x * TI;
    const int tx = threadIdx.x;   // 0..31
    const int ty = threadIdx.y;   // 0..7
    const int tid = ty * 32 + tx;

    __shared__ float4 sd4[TI * NN];        // padded dist: 8 KB
    __shared__ ull    xs2[NROWS * FF];     // pre-packed x rows: 12 KB
    __shared__ float4 As[NROWS * 32];      // A' tile [row][k-quad]: 6 KB

    // Load + pad distances slice d[b, i0:i0+4, :, :].
    {
        const float* dbase = dist + (size_t)(b * NN + i0) * NN * COOR;
        #pragma unroll
        for (int t = tid; t < TI * NN; t += 256) {
            const int e = t * COOR;
            sd4[t] = make_float4(dbase[e], dbase[e + 1], dbase[e + 2], 0.0f);
        }
    }

    // Load this block's 12 x-rows (contiguous 1536 floats), pre-packed.
    {
        const float4* xbase = reinterpret_cast<const float4*>(
            x + (size_t)(b * NN + i0) * COOR * FF);
        #pragma unroll
        for (int t = tid; t < NROWS * FF / 4; t += 256) {
            const float4 v = xbase[t];
            ulonglong2* dst = reinterpret_cast<ulonglong2*>(&xs2[4 * t]);
            dst[0] = make_ulonglong2(pack2(v.x, v.x), pack2(v.y, v.y));
            dst[1] = make_ulonglong2(pack2(v.z, v.z), pack2(v.w, v.w));
        }
    }
    __syncthreads();

    // ---- Prologue: compute A' rows. ty -> row ty, and row ty+8 if ty<4.
    {
        const float4* w1p = reinterpret_cast<const float4*>(w) + tx;  // w1[f][k-quad]
        F4U bq;
        bq.f4 = reinterpret_cast<const float4*>(bv)[tx];

        ull a0l = bq.u[0], a0h = bq.u[1];
        ull a1l = bq.u[0], a1h = bq.u[1];
        const ull* x0 = &xs2[(size_t)ty * FF];
        const ull* x1 = &xs2[(size_t)(ty + 8) * FF];
        const bool two = (ty < 4);

        #pragma unroll 8
        for (int f = 0; f < FF; f++) {
            F4U wv;
            wv.f4 = w1p[f * (FILT / 4)];   // same addr across ty: L1 broadcast
            const ull xp0 = x0[f];
            a0l = fma2(xp0, wv.u[0], a0l);
            a0h = fma2(xp0, wv.u[1], a0h);
            if (two) {
                const ull xp1 = x1[f];
                a1l = fma2(xp1, wv.u[0], a1l);
                a1h = fma2(xp1, wv.u[1], a1h);
            }
        }

        F4U r0; r0.u[0] = a0l; r0.u[1] = a0h;
        As[ty * 32 + tx] = r0.f4;
        if (two) {
            F4U r1; r1.u[0] = a1l; r1.u[1] = a1h;
            As[(ty + 8) * 32 + tx] = r1.f4;
        }
    }
    __syncthreads();

    // A' tile into registers: Ar[i][c] = As[i*COOR + c][tx].
    float4 Ar[TI][COOR];
    #pragma unroll
    for (int i = 0; i < TI; i++)
        #pragma unroll
        for (int c = 0; c < COOR; c++)
            Ar[i][c] = As[(i * COOR + c) * 32 + tx];

    const float4* C4 = reinterpret_cast<const float4*>(g_C) +
                       (size_t)b * NN * COOR * (FILT / 4) + tx;
    float4* out4 = reinterpret_cast<float4*>(out) +
                   ((size_t)(b * NN + i0) * NN) * (FILT / 4) + tx;

    // Prime C pipeline with j = ty.
    float4 c0 = C4[(size_t)ty * COOR * (FILT / 4) + 0 * (FILT / 4)];
    float4 c1 = C4[(size_t)ty * COOR * (FILT / 4) + 1 * (FILT / 4)];
    float4 c2 = C4[(size_t)ty * COOR * (FILT / 4) + 2 * (FILT / 4)];

    #pragma unroll
    for (int it = 0; it < NN / 8; it++) {
        const int j = ty + it * 8;

        float4 n0, n1, n2;
        if (it + 1 < NN / 8) {
            const size_t nb = (size_t)(j + 8) * COOR * (FILT / 4);
            n0 = C4[nb + 0 * (FILT / 4)];
            n1 = C4[nb + 1 * (FILT / 4)];
            n2 = C4[nb + 2 * (FILT / 4)];
        }

        #pragma unroll
        for (int i = 0; i < TI; i++) {
            const float4 dv = sd4[i * NN + j];   // one LDS.128 broadcast
            const float d0 = dv.x, d1 = dv.y, d2 = dv.z;

            float4 o;
            o.x = fmaf(Ar[i][0].x + c0.x, d0,
                  fmaf(Ar[i][1].x + c1.x, d1, (Ar[i][2].x + c2.x) * d2));
            o.y = fmaf(Ar[i][0].y + c0.y, d0,
                  fmaf(Ar[i][1].y + c1.y, d1, (Ar[i][2].y + c2.y) * d2));
            o.z = fmaf(Ar[i][0].z + c0.z, d0,
                  fmaf(Ar[i][1].z + c1.z, d1, (Ar[i][2].z + c2.z) * d2));
            o.w = fmaf(Ar[i][0].w + c0.w, d0,
                  fmaf(Ar[i][1].w + c1.w, d1, (Ar[i][2].w + c2.w) * d2));

            out4[((size_t)i * NN + j) * (FILT / 4)] = o;
        }

        c0 = n0; c1 = n1; c2 = n2;
    }
}

extern "C" void kernel_launch(void* const* d_in, const int* in_sizes, int n_in,
                              void* d_out, int out_size)
{
    const float* x    = (const float*)d_in[0];  // vector_features [8,128,3,128]
    const float* dist = (const float*)d_in[1];  // distances       [8,128,128,3]
    const float* w    = (const float*)d_in[2];  // w_vs            [256,128]
    const float* bv   = (const float*)d_in[3];  // b_vs            [128]
    float* out = (float*)d_out;                 // [8,128,128,128]

    (void)in_sizes; (void)n_in; (void)out_size;

    phase1_kernel<<<dim3((BB * NN * COOR) / 8, 2), 128>>>(x, w);
    phase2_kernel<<<dim3(NN / 4, BB), dim3(32, 8)>>>(x, w, bv, dist, out);
}

// round 17
// speedup vs baseline: 1.0662x; 1.0662x over previous
#include <cuda_runtime.h>
#include <cstdint>

#define BB   8
#define NN   128
#define COOR 3
#define FF   128
#define FILT 128

// Scratch: A' = x @ w1 + bv  and  C = x @ w2, each [B, N, COOR, FILT]
__device__ float g_A[BB * NN * COOR * FILT];
__device__ float g_C[BB * NN * COOR * FILT];

// ---- packed f32x2 helpers (phase 1 only) ----------------------------------
typedef unsigned long long ull;

union F2U {
    float2 f2;
    ull    u;
};

__device__ __forceinline__ ull fma2(ull a, ull b, ull c) {
    ull r;
    asm("fma.rn.f32x2 %0, %1, %2, %3;" : "=l"(r) : "l"(a), "l"(b), "l"(c));
    return r;
}
__device__ __forceinline__ ull pack2(float lo, float hi) {
    ull r;
    asm("mov.b64 %0, {%1, %2};" : "=l"(r) : "r"(__float_as_uint(lo)), "r"(__float_as_uint(hi)));
    return r;
}

// ---------------------------------------------------------------------------
// Phase 1 — R7 configuration VERBATIM (11.4us; partner of the 27.87 best).
// ---------------------------------------------------------------------------
__global__ __launch_bounds__(128) void phase1_kernel(
    const float* __restrict__ x,   // [3072, 128]
    const float* __restrict__ w,   // [256, 128]
    const float* __restrict__ bv)  // [128]
{
    constexpr int RT    = 8;
    constexpr int DEPTH = 8;
    const int r0   = blockIdx.x * RT;
    const int kh   = blockIdx.y * 64;
    const int warp = threadIdx.x >> 5;
    const int lane = threadIdx.x & 31;
    const int k    = kh + lane * 2;
    const int wr   = warp * 2;

    __shared__ float xs[RT][FF];

    {
        const float4* xin = reinterpret_cast<const float4*>(x + (size_t)r0 * FF);
        float4* xs4 = reinterpret_cast<float4*>(&xs[0][0]);
        #pragma unroll
        for (int t = threadIdx.x; t < RT * FF / 4; t += 128) xs4[t] = xin[t];
    }
    __syncthreads();

    ull acc[2][2];
    {
        const float2 b2 = *reinterpret_cast<const float2*>(bv + k);
        const ull bp = pack2(b2.x, b2.y);
        acc[0][0] = bp; acc[0][1] = 0ull;
        acc[1][0] = bp; acc[1][1] = 0ull;
    }

    const float* w1base = w + k;
    const float* w2base = w + (size_t)FF * FILT + k;

    F2U W1[DEPTH], W2[DEPTH];
    #pragma unroll
    for (int d = 0; d < DEPTH; d++) {
        W1[d].f2 = *reinterpret_cast<const float2*>(w1base + (size_t)d * FILT);
        W2[d].f2 = *reinterpret_cast<const float2*>(w2base + (size_t)d * FILT);
    }

    #pragma unroll 8
    for (int f = 0; f < FF; f++) {
        const int slot = f % DEPTH;

        const float xv0 = xs[wr + 0][f];
        const float xv1 = xs[wr + 1][f];
        const ull xp0 = pack2(xv0, xv0);
        const ull xp1 = pack2(xv1, xv1);

        const ull w1v = W1[slot].u;
        const ull w2v = W2[slot].u;

        acc[0][0] = fma2(xp0, w1v, acc[0][0]);
        acc[0][1] = fma2(xp0, w2v, acc[0][1]);
        acc[1][0] = fma2(xp1, w1v, acc[1][0]);
        acc[1][1] = fma2(xp1, w2v, acc[1][1]);

        if (f + DEPTH < FF) {
            W1[slot].f2 = *reinterpret_cast<const float2*>(w1base + (size_t)(f + DEPTH) * FILT);
            W2[slot].f2 = *reinterpret_cast<const float2*>(w2base + (size_t)(f + DEPTH) * FILT);
        }
    }

    #pragma unroll
    for (int r = 0; r < 2; r++) {
        const size_t row = (size_t)(r0 + wr + r);
        F2U oa; oa.u = acc[r][0];
        F2U oc; oc.u = acc[r][1];
        *reinterpret_cast<float2*>(&g_A[row * FILT + k]) = oa.f2;
        *reinterpret_cast<float2*>(&g_C[row * FILT + k]) = oc.f2;
    }
}

// ---------------------------------------------------------------------------
// Phase 2: out[b,i,j,k] = sum_c (A'[b,i,c,k] + C[b,j,c,k]) * d[b,i,j,c]
// CLEAN occupancy experiment (R11 was confounded by TI=2's doubled C
// traffic): TI=4 + JS=2. Same total C/dist traffic, half-size blocks,
// grid (32,2,8)=512, regs trimmed (no C-prefetch; it measured neutral) so
// __launch_bounds__(256,3) holds 3 blocks/SM = 24 warps/SM (was 16, with
// a 108/40 two-vs-one block imbalance). Tail: 1.15 waves of half-blocks
// ~ +7%. Scalar FMA, padded-dist smem, A' in regs — all proven pieces.
// ---------------------------------------------------------------------------
__global__ __launch_bounds__(256, 3) void phase2_kernel(
    const float* __restrict__ dist,  // [B, N, N, COOR]
    float* __restrict__ out)         // [B, N, N, FILT]
{
    constexpr int TI = 4;
    constexpr int JT = 64;           // j per block (JS=2)
    const int b  = blockIdx.z;
    const int i0 = blockIdx.x * TI;
    const int j0 = blockIdx.y * JT;
    const int tx = threadIdx.x;   // 0..31
    const int ty = threadIdx.y;   // 0..7
    const int tid = ty * 32 + tx;

    __shared__ float4 sd4[TI * JT];   // padded (d0,d1,d2,_) per (i,jl): 4 KB

    // Load + pad distances slice d[b, i0:i0+4, j0:j0+64, :].
    {
        const float* dbase = dist + ((size_t)(b * NN + i0) * NN + j0) * COOR;
        #pragma unroll
        for (int t = tid; t < TI * JT; t += 256) {
            const int i  = t / JT;
            const int jl = t % JT;
            const float* p = dbase + (size_t)i * NN * COOR + jl * COOR;
            sd4[t] = make_float4(p[0], p[1], p[2], 0.0f);
        }
    }

    // A' tile into registers: 4 i x 3 c x float4 = 48 regs.
    float4 Ar[TI][COOR];
    {
        const float4* A4 = reinterpret_cast<const float4*>(g_A);
        #pragma unroll
        for (int i = 0; i < TI; i++)
            #pragma unroll
            for (int c = 0; c < COOR; c++)
                Ar[i][c] = A4[((size_t)(b * NN + i0 + i) * COOR + c) * (FILT / 4) + tx];
    }
    __syncthreads();

    const float4* C4 = reinterpret_cast<const float4*>(g_C) +
                       ((size_t)(b * NN + j0)) * COOR * (FILT / 4) + tx;
    float4* out4 = reinterpret_cast<float4*>(out) +
                   ((size_t)(b * NN + i0) * NN + j0) * (FILT / 4) + tx;

    #pragma unroll 2
    for (int it = 0; it < JT / 8; it++) {
        const int jl = ty + it * 8;        // local j in [0, 64)

        const size_t cb = (size_t)jl * COOR * (FILT / 4);
        const float4 c0 = C4[cb + 0 * (FILT / 4)];
        const float4 c1 = C4[cb + 1 * (FILT / 4)];
        const float4 c2 = C4[cb + 2 * (FILT / 4)];

        #pragma unroll
        for (int i = 0; i < TI; i++) {
            const float4 dv = sd4[i * JT + jl];   // one LDS.128 broadcast
            const float d0 = dv.x, d1 = dv.y, d2 = dv.z;

            float4 o;
            o.x = fmaf(Ar[i][0].x + c0.x, d0,
                  fmaf(Ar[i][1].x + c1.x, d1, (Ar[i][2].x + c2.x) * d2));
            o.y = fmaf(Ar[i][0].y + c0.y, d0,
                  fmaf(Ar[i][1].y + c1.y, d1, (Ar[i][2].y + c2.y) * d2));
            o.z = fmaf(Ar[i][0].z + c0.z, d0,
                  fmaf(Ar[i][1].z + c1.z, d1, (Ar[i][2].z + c2.z) * d2));
            o.w = fmaf(Ar[i][0].w + c0.w, d0,
                  fmaf(Ar[i][1].w + c1.w, d1, (Ar[i][2].w + c2.w) * d2));

            out4[((size_t)i * NN + jl) * (FILT / 4)] = o;
        }
    }
}

extern "C" void kernel_launch(void* const* d_in, const int* in_sizes, int n_in,
                              void* d_out, int out_size)
{
    const float* x    = (const float*)d_in[0];  // vector_features [8,128,3,128]
    const float* dist = (const float*)d_in[1];  // distances       [8,128,128,3]
    const float* w    = (const float*)d_in[2];  // w_vs            [256,128]
    const float* bv   = (const float*)d_in[3];  // b_vs            [128]
    float* out = (float*)d_out;                 // [8,128,128,128]

    (void)in_sizes; (void)n_in; (void)out_size;

    phase1_kernel<<<dim3((BB * NN * COOR) / 8, 2), 128>>>(x, w, bv);
    phase2_kernel<<<dim3(NN / 4, 2, BB), dim3(32, 8)>>>(dist, out);
}